// round 5
// baseline (speedup 1.0000x reference)
#include <cuda_runtime.h>
#include <cuda_fp16.h>
#include <cstdint>

// out[n,d] = sum_m softmax_m( w2 . tanh(x[m,n,:] @ W1 + b1) ) * x[m,n,d]
// M=8, N=100000, D=256, H=128.
// Per CTA: 16 nodes x 8 metapaths = 128 GEMM rows. A tile fp32 resident in
// smem (exact weighted-sum source); GEMM via mma.sync m16n8k16 fp16 with
// on-the-fly fp32->fp16 A fragments; W1 pre-baked fp16 swizzled for ldmatrix.

constexpr int TN  = 16;
constexpr int NTH = 512;

// smem offsets from 1024B-aligned base
constexpr int SM_A    = 0;        // 131072 B : A tile fp32, swizzled
constexpr int SM_W1   = 131072;   //  65536 B : W1 fp16 image [256 k][128 j], swizzled
constexpr int SM_PART = 196608;   //   1024 B : logit partials [128][2]
constexpr int SM_ATT  = 197632;   //    512 B
constexpr int SM_B1   = 198144;   //    512 B
constexpr int SM_W2   = 198656;   //    512 B
constexpr int SM_BYTES = 199168 + 1024;

__host__ __device__ __forceinline__ int swA(int b) { return b ^ (((b >> 10) & 7) << 5); }
__host__ __device__ __forceinline__ int swW(int b) { return b ^ (((b >> 8) & 7) << 4); }

// ---------------- smem asm helpers (u32 shared addresses) ------------------
__device__ __forceinline__ void sts128(uint32_t a, float4 v) {
    asm volatile("st.shared.v4.f32 [%0], {%1,%2,%3,%4};"
                 :: "r"(a), "f"(v.x), "f"(v.y), "f"(v.z), "f"(v.w) : "memory");
}
__device__ __forceinline__ float4 lds128(uint32_t a) {
    float4 v;
    asm volatile("ld.shared.v4.f32 {%0,%1,%2,%3}, [%4];"
                 : "=f"(v.x), "=f"(v.y), "=f"(v.z), "=f"(v.w) : "r"(a));
    return v;
}
__device__ __forceinline__ float2 lds64(uint32_t a) {
    float2 v;
    asm volatile("ld.shared.v2.f32 {%0,%1}, [%2];" : "=f"(v.x), "=f"(v.y) : "r"(a));
    return v;
}
__device__ __forceinline__ float lds32(uint32_t a) {
    float v; asm volatile("ld.shared.f32 %0, [%1];" : "=f"(v) : "r"(a)); return v;
}
__device__ __forceinline__ void sts32(uint32_t a, float v) {
    asm volatile("st.shared.f32 [%0], %1;" :: "r"(a), "f"(v) : "memory");
}
__device__ __forceinline__ void sts128u(uint32_t a, uint4 v) {
    asm volatile("st.shared.v4.b32 [%0], {%1,%2,%3,%4};"
                 :: "r"(a), "r"(v.x), "r"(v.y), "r"(v.z), "r"(v.w) : "memory");
}
__device__ __forceinline__ uint4 ldmx4t(uint32_t a) {
    uint4 r;
    asm volatile("ldmatrix.sync.aligned.m8n8.x4.trans.shared.b16 {%0,%1,%2,%3}, [%4];"
                 : "=r"(r.x), "=r"(r.y), "=r"(r.z), "=r"(r.w) : "r"(a));
    return r;
}
__device__ __forceinline__ void mma16816(float* c, uint32_t a0, uint32_t a1,
                                         uint32_t a2, uint32_t a3,
                                         uint32_t b0, uint32_t b1) {
    asm volatile("mma.sync.aligned.m16n8k16.row.col.f32.f16.f16.f32 "
                 "{%0,%1,%2,%3}, {%4,%5,%6,%7}, {%8,%9}, {%0,%1,%2,%3};"
                 : "+f"(c[0]), "+f"(c[1]), "+f"(c[2]), "+f"(c[3])
                 : "r"(a0), "r"(a1), "r"(a2), "r"(a3), "r"(b0), "r"(b1));
}
__device__ __forceinline__ uint32_t packh2(float lo, float hi) {
    __half2 h = __floats2half2_rn(lo, hi);
    return *reinterpret_cast<uint32_t*>(&h);
}
__device__ __forceinline__ float fast_tanh(float x) {
    float e = __expf(2.0f * x);
    return 1.0f - __fdividef(2.0f, e + 1.0f);
}

// ---- W1 pre-bake: fp16, [K=256 rows][H=128 cols], 256B rows, swW swizzle ----
__device__ __align__(16) __half g_w1img[256 * 128];

__global__ void prep_w1_kernel(const float* __restrict__ W1) {
    int idx = blockIdx.x * blockDim.x + threadIdx.x;   // d*128 + j
    if (idx >= 256 * 128) return;
    int d = idx >> 7, j = idx & 127;
    int b = swW(d * 256 + j * 2);
    g_w1img[b >> 1] = __float2half_rn(W1[idx]);
}

// --------------------------------- main -----------------------------------
__global__ __launch_bounds__(NTH, 1)
void hete_kernel(const float* __restrict__ homo, const float* __restrict__ b1g,
                 const float* __restrict__ w2g, float* __restrict__ out, int Nn) {
    extern __shared__ char smraw[];
    uint32_t raw;
    asm("{ .reg .u64 t; cvta.to.shared.u64 t, %1; cvt.u32.u64 %0, t; }"
        : "=r"(raw) : "l"(smraw));
    const uint32_t base = (raw + 1023u) & ~1023u;

    const int tid = threadIdx.x, wid = tid >> 5, lane = tid & 31;
    const int n0 = blockIdx.x * TN;

    // W1 fp16 image copy (pre-swizzled): 65536 B = 4096 uint4
    {
        const uint4* src = (const uint4*)g_w1img;
        #pragma unroll
        for (int k = 0; k < 8; k++) {
            int i = k * NTH + tid;
            sts128u(base + SM_W1 + i * 16, src[i]);
        }
    }
    if (tid < 128) {
        sts32(base + SM_B1 + tid * 4, b1g[tid]);
        sts32(base + SM_W2 + tid * 4, w2g[tid]);
    }

    // A tile fp32: 128 rows x 64 float4, swA swizzle
    {
        const float4* homo4 = (const float4*)homo;
        #pragma unroll 1
        for (int kk = 0; kk < 16; kk += 8) {
            float4 v[8];
            #pragma unroll
            for (int u = 0; u < 8; u++) {
                int idx = (kk + u) * NTH + tid;
                int row = idx >> 6, d4 = idx & 63;
                int m = row >> 4, i = row & 15;
                int n = n0 + i; if (n >= Nn) n = Nn - 1;
                v[u] = homo4[((size_t)m * Nn + n) * 64 + d4];
            }
            #pragma unroll
            for (int u = 0; u < 8; u++) {
                int idx = (kk + u) * NTH + tid;
                int row = idx >> 6, d4 = idx & 63;
                sts128(base + SM_A + swA(row * 1024 + d4 * 16), v[u]);
            }
        }
    }
    __syncthreads();

    // ---------------- GEMM: warp = (row block rb, H-half hh) ----------------
    const int rb = wid & 7;        // 16-row block
    const int hh = wid >> 3;       // 64-col half of H
    const int gr = lane >> 2;      // fragment group row 0..7
    const int qk = (lane & 3) * 2; // fragment k pair within 8

    float acc[32];
    #pragma unroll
    for (int i = 0; i < 32; i++) acc[i] = 0.0f;

    // ldmatrix.x4 lane address: rows k0 + (lane&7) + 8*bit3, col block +8*bit4
    const int lrow  = (lane & 7) + ((lane >> 3) & 1) * 8;
    const int lcolB = hh * 64 + ((lane >> 4) & 1) * 8;
    const int r0 = rb * 16 + gr;

    #pragma unroll 4
    for (int ks = 0; ks < 16; ks++) {
        const int k0 = ks * 16;
        // A fragment: fp32 smem loads + pack to fp16
        float2 v00 = lds64(base + SM_A + swA(r0 * 1024 + (k0 + qk) * 4));
        float2 v01 = lds64(base + SM_A + swA(r0 * 1024 + (k0 + qk + 8) * 4));
        float2 v10 = lds64(base + SM_A + swA((r0 + 8) * 1024 + (k0 + qk) * 4));
        float2 v11 = lds64(base + SM_A + swA((r0 + 8) * 1024 + (k0 + qk + 8) * 4));
        uint32_t a0 = packh2(v00.x, v00.y);
        uint32_t a1 = packh2(v10.x, v10.y);
        uint32_t a2 = packh2(v01.x, v01.y);
        uint32_t a3 = packh2(v11.x, v11.y);

        #pragma unroll
        for (int np = 0; np < 4; np++) {
            int nt = np * 2;
            uint32_t wAddr = base + SM_W1 +
                swW((k0 + lrow) * 256 + (lcolB + nt * 8) * 2);
            uint4 bb = ldmx4t(wAddr);   // m0/m1: ntile nt (k-lo/k-hi); m2/m3: nt+1
            mma16816(acc + nt * 4,       a0, a1, a2, a3, bb.x, bb.y);
            mma16816(acc + (nt + 1) * 4, a0, a1, a2, a3, bb.z, bb.w);
        }
    }

    // ---------------- logits: tanh + dot(w2), quad reduce -------------------
    float s0 = 0.0f, s1 = 0.0f;
    #pragma unroll
    for (int nt = 0; nt < 8; nt++) {
        int col = hh * 64 + nt * 8 + qk;
        float b1a = lds32(base + SM_B1 + col * 4);
        float b1b = lds32(base + SM_B1 + col * 4 + 4);
        float w2a = lds32(base + SM_W2 + col * 4);
        float w2b = lds32(base + SM_W2 + col * 4 + 4);
        s0 += fast_tanh(acc[nt * 4 + 0] + b1a) * w2a
            + fast_tanh(acc[nt * 4 + 1] + b1b) * w2b;
        s1 += fast_tanh(acc[nt * 4 + 2] + b1a) * w2a
            + fast_tanh(acc[nt * 4 + 3] + b1b) * w2b;
    }
    s0 += __shfl_xor_sync(0xffffffffu, s0, 1);
    s0 += __shfl_xor_sync(0xffffffffu, s0, 2);
    s1 += __shfl_xor_sync(0xffffffffu, s1, 1);
    s1 += __shfl_xor_sync(0xffffffffu, s1, 2);
    if ((lane & 3) == 0) {
        sts32(base + SM_PART + ((rb * 16 + gr) * 2 + hh) * 4, s0);
        sts32(base + SM_PART + ((rb * 16 + gr + 8) * 2 + hh) * 4, s1);
    }
    __syncthreads();

    // ---------------- softmax over m (16 threads, one per node) -------------
    if (tid < TN) {
        float lg[8]; float mx = -1e30f;
        #pragma unroll
        for (int m = 0; m < 8; m++) {
            int r = m * 16 + tid;
            float s = lds32(base + SM_PART + (r * 2) * 4)
                    + lds32(base + SM_PART + (r * 2 + 1) * 4);
            lg[m] = s; mx = fmaxf(mx, s);
        }
        float ss = 0.0f;
        #pragma unroll
        for (int m = 0; m < 8; m++) { lg[m] = __expf(lg[m] - mx); ss += lg[m]; }
        float inv = __fdividef(1.0f, ss);
        #pragma unroll
        for (int m = 0; m < 8; m++) sts32(base + SM_ATT + (m * 16 + tid) * 4, lg[m] * inv);
    }
    __syncthreads();

    // ---------- weighted sum from exact fp32 A tile (warp = node) -----------
    {
        int i = wid;               // node 0..15, one warp per node
        int n = n0 + i;
        if (n < Nn) {
            float a[8];
            #pragma unroll
            for (int m = 0; m < 8; m++) a[m] = lds32(base + SM_ATT + (m * 16 + i) * 4);
            #pragma unroll
            for (int half = 0; half < 2; half++) {
                int d4 = lane + 32 * half;   // float4 chunk 0..63
                float4 accv = make_float4(0.f, 0.f, 0.f, 0.f);
                #pragma unroll
                for (int m = 0; m < 8; m++) {
                    int row = m * 16 + i;
                    float4 v = lds128(base + SM_A + swA(row * 1024 + d4 * 16));
                    accv.x += a[m] * v.x; accv.y += a[m] * v.y;
                    accv.z += a[m] * v.z; accv.w += a[m] * v.w;
                }
                ((float4*)out)[(size_t)n * 64 + d4] = accv;
            }
        }
    }
}

extern "C" void kernel_launch(void* const* d_in, const int* in_sizes, int n_in,
                              void* d_out, int out_size) {
    const float* homo = (const float*)d_in[1];
    const float* W1   = (const float*)d_in[2];
    const float* b1   = (const float*)d_in[3];
    const float* W2   = (const float*)d_in[4];
    // b2 is a scalar added to every logit -> cancels in softmax over m; ignored.
    int Nn = in_sizes[0];

    cudaFuncSetAttribute(hete_kernel, cudaFuncAttributeMaxDynamicSharedMemorySize, SM_BYTES);
    prep_w1_kernel<<<(256 * 128 + 255) / 256, 256>>>(W1);
    int grid = (Nn + TN - 1) / TN;
    hete_kernel<<<grid, NTH, SM_BYTES>>>(homo, b1, W2, (float*)d_out, Nn);
}

// round 6
// speedup vs baseline: 1.2708x; 1.2708x over previous
#include <cuda_runtime.h>
#include <cuda_fp16.h>
#include <cstdint>

// out[n,d] = sum_m softmax_m( w2 . tanh(x[m,n,:] @ W1 + b1) ) * x[m,n,d]
// M=8, N=100000, D=256, H=128.
// Per CTA: 8 nodes x 8 metapaths = 64 GEMM rows. A tile stored fp16 in smem
// (MMA operand via ldmatrix AND weighted-sum source); W1 fp16 pre-swizzled.
// 2 CTAs/SM (99 KB smem each) for cross-CTA phase overlap.

constexpr int TN  = 8;
constexpr int NTH = 512;

// smem offsets from 1024B-aligned base
constexpr int SM_A    = 0;        // 32768 B : A tile fp16 [64 rows][256 k], swizzled
constexpr int SM_W1   = 32768;    // 65536 B : W1 fp16 image [256 k][128 j], swizzled
constexpr int SM_PART = 98304;    //  1024 B : logit partials [64][4]
constexpr int SM_ATT  = 99328;    //   256 B
constexpr int SM_B1   = 99584;    //   512 B
constexpr int SM_W2   = 100096;   //   512 B
constexpr int SM_BYTES = 100608 + 1024;

// A swizzle: 512B rows; XOR byte bits[4:6] with row&7  (row = b>>9)
__host__ __device__ __forceinline__ int swA(int b) { return b ^ (((b >> 9) & 7) << 4); }
// W1 swizzle: 256B rows; XOR byte bits[4:6] with (b>>8)&7
__host__ __device__ __forceinline__ int swW(int b) { return b ^ (((b >> 8) & 7) << 4); }

// ---------------- smem asm helpers (u32 shared addresses) ------------------
__device__ __forceinline__ float lds32(uint32_t a) {
    float v; asm volatile("ld.shared.f32 %0, [%1];" : "=f"(v) : "r"(a)); return v;
}
__device__ __forceinline__ void sts32(uint32_t a, float v) {
    asm volatile("st.shared.f32 [%0], %1;" :: "r"(a), "f"(v) : "memory");
}
__device__ __forceinline__ void sts64u(uint32_t a, uint2 v) {
    asm volatile("st.shared.v2.b32 [%0], {%1,%2};" :: "r"(a), "r"(v.x), "r"(v.y) : "memory");
}
__device__ __forceinline__ uint2 lds64u(uint32_t a) {
    uint2 v;
    asm volatile("ld.shared.v2.b32 {%0,%1}, [%2];" : "=r"(v.x), "=r"(v.y) : "r"(a));
    return v;
}
__device__ __forceinline__ void sts128u(uint32_t a, uint4 v) {
    asm volatile("st.shared.v4.b32 [%0], {%1,%2,%3,%4};"
                 :: "r"(a), "r"(v.x), "r"(v.y), "r"(v.z), "r"(v.w) : "memory");
}
__device__ __forceinline__ uint4 ldmx4(uint32_t a) {           // non-transposed
    uint4 r;
    asm volatile("ldmatrix.sync.aligned.m8n8.x4.shared.b16 {%0,%1,%2,%3}, [%4];"
                 : "=r"(r.x), "=r"(r.y), "=r"(r.z), "=r"(r.w) : "r"(a));
    return r;
}
__device__ __forceinline__ uint4 ldmx4t(uint32_t a) {          // transposed
    uint4 r;
    asm volatile("ldmatrix.sync.aligned.m8n8.x4.trans.shared.b16 {%0,%1,%2,%3}, [%4];"
                 : "=r"(r.x), "=r"(r.y), "=r"(r.z), "=r"(r.w) : "r"(a));
    return r;
}
__device__ __forceinline__ void mma16816(float* c, uint32_t a0, uint32_t a1,
                                         uint32_t a2, uint32_t a3,
                                         uint32_t b0, uint32_t b1) {
    asm volatile("mma.sync.aligned.m16n8k16.row.col.f32.f16.f16.f32 "
                 "{%0,%1,%2,%3}, {%4,%5,%6,%7}, {%8,%9}, {%0,%1,%2,%3};"
                 : "+f"(c[0]), "+f"(c[1]), "+f"(c[2]), "+f"(c[3])
                 : "r"(a0), "r"(a1), "r"(a2), "r"(a3), "r"(b0), "r"(b1));
}
__device__ __forceinline__ uint32_t packh2(float lo, float hi) {
    __half2 h = __floats2half2_rn(lo, hi);
    return *reinterpret_cast<uint32_t*>(&h);
}
__device__ __forceinline__ float fast_tanh(float x) {
    float e = __expf(2.0f * x);
    return 1.0f - __fdividef(2.0f, e + 1.0f);
}

// ---- W1 pre-bake: fp16, [K=256 rows][H=128 cols], 256B rows, swW swizzle ----
__device__ __align__(16) __half g_w1img[256 * 128];

__global__ void prep_w1_kernel(const float* __restrict__ W1) {
    int idx = blockIdx.x * blockDim.x + threadIdx.x;   // d*128 + j
    if (idx >= 256 * 128) return;
    int d = idx >> 7, j = idx & 127;
    int b = swW(d * 256 + j * 2);
    g_w1img[b >> 1] = __float2half_rn(W1[idx]);
}

// --------------------------------- main -----------------------------------
__global__ __launch_bounds__(NTH, 2)
void hete_kernel(const float* __restrict__ homo, const float* __restrict__ b1g,
                 const float* __restrict__ w2g, float* __restrict__ out, int Nn) {
    extern __shared__ char smraw[];
    uint32_t raw;
    asm("{ .reg .u64 t; cvta.to.shared.u64 t, %1; cvt.u32.u64 %0, t; }"
        : "=r"(raw) : "l"(smraw));
    const uint32_t base = (raw + 1023u) & ~1023u;

    const int tid = threadIdx.x, wid = tid >> 5, lane = tid & 31;
    const int n0 = blockIdx.x * TN;

    if (tid < 128) {
        sts32(base + SM_B1 + tid * 4, b1g[tid]);
        sts32(base + SM_W2 + tid * 4, w2g[tid]);
    }

    // A tile fp16: 64 rows x 512B, swA swizzle. 4096 float4 / 512 thr = 8 each.
    {
        const float4* homo4 = (const float4*)homo;
        #pragma unroll 1
        for (int kk = 0; kk < 8; kk += 4) {
            float4 v[4];
            #pragma unroll
            for (int u = 0; u < 4; u++) {
                int idx = (kk + u) * NTH + tid;
                int row = idx >> 6, d4 = idx & 63;
                int m = row >> 3, i = row & 7;
                int n = n0 + i; if (n >= Nn) n = Nn - 1;
                v[u] = homo4[((size_t)m * Nn + n) * 64 + d4];
            }
            #pragma unroll
            for (int u = 0; u < 4; u++) {
                int idx = (kk + u) * NTH + tid;
                int row = idx >> 6, d4 = idx & 63;
                uint2 p;
                p.x = packh2(v[u].x, v[u].y);
                p.y = packh2(v[u].z, v[u].w);
                sts64u(base + SM_A + swA(row * 512 + d4 * 8), p);
            }
        }
    }

    // W1 fp16 image copy (pre-swizzled): 65536 B = 4096 uint4 / 512 = 8 each
    {
        const uint4* src = (const uint4*)g_w1img;
        #pragma unroll
        for (int k = 0; k < 8; k++) {
            int i = k * NTH + tid;
            sts128u(base + SM_W1 + i * 16, src[i]);
        }
    }
    __syncthreads();

    // ------------- GEMM: warp = (row block rb 0..3, col quad hq 0..3) -------
    const int rb = wid & 3;          // 16-row block
    const int hq = wid >> 2;         // 32-col quarter of H
    const int gr = lane >> 2;        // fragment group row 0..7
    const int qk = (lane & 3) * 2;   // fragment col pair within 8

    float acc[16];
    #pragma unroll
    for (int i = 0; i < 16; i++) acc[i] = 0.0f;

    // A ldmatrix lane addressing: m0 rows r0..r0+7 klo, m1 rows+8 klo, m2 khi, m3 rows+8 khi
    const int arow = rb * 16 + ((lane >> 3) & 1) * 8 + (lane & 7);
    const uint32_t aRowBase = base + SM_A + arow * 512;
    const uint32_t aXor = (uint32_t)((arow & 7) << 4);
    const uint32_t aK16 = (uint32_t)(((lane >> 4) & 1) * 16);
    // B ldmatrix lane addressing (transposed)
    const int lrow  = (lane & 7) + ((lane >> 3) & 1) * 8;   // k-row within 16
    const int bcol8 = ((lane >> 4) & 1) * 8;                // 8-col group

    #pragma unroll 4
    for (int ks = 0; ks < 16; ks++) {
        uint4 aa = ldmx4(aRowBase + (((uint32_t)ks * 32 + aK16) ^ aXor));
        #pragma unroll
        for (int j = 0; j < 2; j++) {
            int cb = hq * 32 + j * 16;
            uint32_t wAddr = base + SM_W1 +
                swW((ks * 16 + lrow) * 256 + (cb + bcol8) * 2);
            uint4 bb = ldmx4t(wAddr);   // m0/m1: n-tile 2j (k-lo/hi); m2/m3: 2j+1
            mma16816(acc + (2 * j) * 4,     aa.x, aa.y, aa.z, aa.w, bb.x, bb.y);
            mma16816(acc + (2 * j + 1) * 4, aa.x, aa.y, aa.z, aa.w, bb.z, bb.w);
        }
    }

    // ---------------- logits: tanh + dot(w2), quad reduce -------------------
    float s0 = 0.0f, s1 = 0.0f;
    #pragma unroll
    for (int t = 0; t < 4; t++) {
        int col = hq * 32 + t * 8 + qk;
        float b1a = lds32(base + SM_B1 + col * 4);
        float b1b = lds32(base + SM_B1 + col * 4 + 4);
        float w2a = lds32(base + SM_W2 + col * 4);
        float w2b = lds32(base + SM_W2 + col * 4 + 4);
        s0 += fast_tanh(acc[t * 4 + 0] + b1a) * w2a
            + fast_tanh(acc[t * 4 + 1] + b1b) * w2b;
        s1 += fast_tanh(acc[t * 4 + 2] + b1a) * w2a
            + fast_tanh(acc[t * 4 + 3] + b1b) * w2b;
    }
    s0 += __shfl_xor_sync(0xffffffffu, s0, 1);
    s0 += __shfl_xor_sync(0xffffffffu, s0, 2);
    s1 += __shfl_xor_sync(0xffffffffu, s1, 1);
    s1 += __shfl_xor_sync(0xffffffffu, s1, 2);
    if ((lane & 3) == 0) {
        int r = rb * 16 + gr;
        sts32(base + SM_PART + (r * 4 + hq) * 4, s0);
        sts32(base + SM_PART + ((r + 8) * 4 + hq) * 4, s1);
    }
    __syncthreads();

    // ---------------- softmax over m (8 threads, one per node) --------------
    if (tid < TN) {
        float lg[8]; float mx = -1e30f;
        #pragma unroll
        for (int m = 0; m < 8; m++) {
            int r = m * 8 + tid;
            float s = lds32(base + SM_PART + (r * 4 + 0) * 4)
                    + lds32(base + SM_PART + (r * 4 + 1) * 4)
                    + lds32(base + SM_PART + (r * 4 + 2) * 4)
                    + lds32(base + SM_PART + (r * 4 + 3) * 4);
            lg[m] = s; mx = fmaxf(mx, s);
        }
        float ss = 0.0f;
        #pragma unroll
        for (int m = 0; m < 8; m++) { lg[m] = __expf(lg[m] - mx); ss += lg[m]; }
        float inv = __fdividef(1.0f, ss);
        #pragma unroll
        for (int m = 0; m < 8; m++) sts32(base + SM_ATT + (m * 8 + tid) * 4, lg[m] * inv);
    }
    __syncthreads();

    // ------- weighted sum from fp16 A tile (2 warps per node, uint2/lane) ---
    {
        int node = wid >> 1;
        int c2 = (wid & 1) * 32 + lane;     // 8-byte chunk 0..63 -> one float4 out
        int n = n0 + node;
        if (n < Nn) {
            float a[8];
            #pragma unroll
            for (int m = 0; m < 8; m++) a[m] = lds32(base + SM_ATT + (m * 8 + node) * 4);
            float4 o = make_float4(0.f, 0.f, 0.f, 0.f);
            #pragma unroll
            for (int m = 0; m < 8; m++) {
                int row = m * 8 + node;
                uint2 rawv = lds64u(base + SM_A + swA(row * 512 + c2 * 8));
                float2 f0 = __half22float2(*reinterpret_cast<__half2*>(&rawv.x));
                float2 f1 = __half22float2(*reinterpret_cast<__half2*>(&rawv.y));
                o.x += a[m] * f0.x; o.y += a[m] * f0.y;
                o.z += a[m] * f1.x; o.w += a[m] * f1.y;
            }
            ((float4*)out)[(size_t)n * 64 + c2] = o;
        }
    }
}

extern "C" void kernel_launch(void* const* d_in, const int* in_sizes, int n_in,
                              void* d_out, int out_size) {
    const float* homo = (const float*)d_in[1];
    const float* W1   = (const float*)d_in[2];
    const float* b1   = (const float*)d_in[3];
    const float* W2   = (const float*)d_in[4];
    // b2 is a scalar added to every logit -> cancels in softmax over m; ignored.
    int Nn = in_sizes[0];

    cudaFuncSetAttribute(hete_kernel, cudaFuncAttributeMaxDynamicSharedMemorySize, SM_BYTES);
    prep_w1_kernel<<<(256 * 128 + 255) / 256, 256>>>(W1);
    int grid = (Nn + TN - 1) / TN;
    hete_kernel<<<grid, NTH, SM_BYTES>>>(homo, b1, W2, (float*)d_out, Nn);
}

// round 7
// speedup vs baseline: 1.2786x; 1.0061x over previous
#include <cuda_runtime.h>
#include <cuda_fp16.h>
#include <cstdint>

// out[n,d] = sum_m softmax_m( w2 . tanh(x[m,n,:] @ W1 + b1) ) * x[m,n,d]
// M=8, N=100000, D=256, H=128.
// Per CTA: 8 nodes x 8 metapaths = 64 GEMM rows, A tile fp16 in smem (MMA
// operand via ldmatrix AND weighted-sum source). Warp tile = 32 rows x 16
// cols so each B fragment feeds 2 MMAs. W1 streamed in via cp.async.
// 2 CTAs/SM for cross-CTA phase overlap.

constexpr int TN  = 8;
constexpr int NTH = 512;

// smem offsets from 1024B-aligned base
constexpr int SM_A    = 0;        // 32768 B : A tile fp16 [64 rows][256 k], swizzled
constexpr int SM_W1   = 32768;    // 65536 B : W1 fp16 image [256 k][128 j], swizzled
constexpr int SM_PART = 98304;    //  2048 B : logit partials [64][8]
constexpr int SM_ATT  = 100352;   //   256 B
constexpr int SM_B1   = 100608;   //   512 B
constexpr int SM_W2   = 101120;   //   512 B
constexpr int SM_BYTES = 101632 + 1024;

// A swizzle: 512B rows; XOR byte bits[4:6] with row&7  (row = b>>9)
__host__ __device__ __forceinline__ int swA(int b) { return b ^ (((b >> 9) & 7) << 4); }
// W1 swizzle: 256B rows; XOR byte bits[4:6] with (b>>8)&7
__host__ __device__ __forceinline__ int swW(int b) { return b ^ (((b >> 8) & 7) << 4); }

// ---------------- smem asm helpers (u32 shared addresses) ------------------
__device__ __forceinline__ float lds32(uint32_t a) {
    float v; asm volatile("ld.shared.f32 %0, [%1];" : "=f"(v) : "r"(a)); return v;
}
__device__ __forceinline__ void sts32(uint32_t a, float v) {
    asm volatile("st.shared.f32 [%0], %1;" :: "r"(a), "f"(v) : "memory");
}
__device__ __forceinline__ float4 lds128(uint32_t a) {
    float4 v;
    asm volatile("ld.shared.v4.f32 {%0,%1,%2,%3}, [%4];"
                 : "=f"(v.x), "=f"(v.y), "=f"(v.z), "=f"(v.w) : "r"(a));
    return v;
}
__device__ __forceinline__ void sts64u(uint32_t a, uint2 v) {
    asm volatile("st.shared.v2.b32 [%0], {%1,%2};" :: "r"(a), "r"(v.x), "r"(v.y) : "memory");
}
__device__ __forceinline__ uint2 lds64u(uint32_t a) {
    uint2 v;
    asm volatile("ld.shared.v2.b32 {%0,%1}, [%2];" : "=r"(v.x), "=r"(v.y) : "r"(a));
    return v;
}
__device__ __forceinline__ void cpasync16(uint32_t dst, const void* src) {
    asm volatile("cp.async.cg.shared.global [%0], [%1], 16;"
                 :: "r"(dst), "l"(src) : "memory");
}
__device__ __forceinline__ uint4 ldmx4(uint32_t a) {           // non-transposed
    uint4 r;
    asm volatile("ldmatrix.sync.aligned.m8n8.x4.shared.b16 {%0,%1,%2,%3}, [%4];"
                 : "=r"(r.x), "=r"(r.y), "=r"(r.z), "=r"(r.w) : "r"(a));
    return r;
}
__device__ __forceinline__ uint4 ldmx4t(uint32_t a) {          // transposed
    uint4 r;
    asm volatile("ldmatrix.sync.aligned.m8n8.x4.trans.shared.b16 {%0,%1,%2,%3}, [%4];"
                 : "=r"(r.x), "=r"(r.y), "=r"(r.z), "=r"(r.w) : "r"(a));
    return r;
}
__device__ __forceinline__ void mma16816(float* c, uint32_t a0, uint32_t a1,
                                         uint32_t a2, uint32_t a3,
                                         uint32_t b0, uint32_t b1) {
    asm volatile("mma.sync.aligned.m16n8k16.row.col.f32.f16.f16.f32 "
                 "{%0,%1,%2,%3}, {%4,%5,%6,%7}, {%8,%9}, {%0,%1,%2,%3};"
                 : "+f"(c[0]), "+f"(c[1]), "+f"(c[2]), "+f"(c[3])
                 : "r"(a0), "r"(a1), "r"(a2), "r"(a3), "r"(b0), "r"(b1));
}
__device__ __forceinline__ uint32_t packh2(float lo, float hi) {
    __half2 h = __floats2half2_rn(lo, hi);
    return *reinterpret_cast<uint32_t*>(&h);
}
__device__ __forceinline__ float fast_tanh(float x) {
    float e = __expf(2.0f * x);
    return 1.0f - __fdividef(2.0f, e + 1.0f);
}

// ---- W1 pre-bake: fp16, [K=256 rows][H=128 cols], 256B rows, swW swizzle ----
__device__ __align__(16) __half g_w1img[256 * 128];

__global__ void prep_w1_kernel(const float* __restrict__ W1) {
    int idx = blockIdx.x * blockDim.x + threadIdx.x;   // d*128 + j
    if (idx >= 256 * 128) return;
    int d = idx >> 7, j = idx & 127;
    int b = swW(d * 256 + j * 2);
    g_w1img[b >> 1] = __float2half_rn(W1[idx]);
}

// --------------------------------- main -----------------------------------
__global__ __launch_bounds__(NTH, 2)
void hete_kernel(const float* __restrict__ homo, const float* __restrict__ b1g,
                 const float* __restrict__ w2g, float* __restrict__ out, int Nn) {
    extern __shared__ char smraw[];
    uint32_t raw;
    asm("{ .reg .u64 t; cvta.to.shared.u64 t, %1; cvt.u32.u64 %0, t; }"
        : "=r"(raw) : "l"(smraw));
    const uint32_t base = (raw + 1023u) & ~1023u;

    const int tid = threadIdx.x, wid = tid >> 5, lane = tid & 31;
    const int n0 = blockIdx.x * TN;

    // W1 image -> smem via cp.async (overlaps with A tile LDG below)
    {
        const char* src = (const char*)g_w1img;
        #pragma unroll
        for (int k = 0; k < 8; k++) {
            int i = k * NTH + tid;
            cpasync16(base + SM_W1 + i * 16, src + i * 16);
        }
        asm volatile("cp.async.commit_group;" ::: "memory");
    }
    if (tid < 128) {
        sts32(base + SM_B1 + tid * 4, b1g[tid]);
        sts32(base + SM_W2 + tid * 4, w2g[tid]);
    }

    // A tile fp16: 64 rows x 512B, swA swizzle. 4096 float4 / 512 thr = 8 each.
    {
        const float4* homo4 = (const float4*)homo;
        #pragma unroll 1
        for (int kk = 0; kk < 8; kk += 4) {
            float4 v[4];
            #pragma unroll
            for (int u = 0; u < 4; u++) {
                int idx = (kk + u) * NTH + tid;
                int row = idx >> 6, d4 = idx & 63;
                int m = row >> 3, i = row & 7;
                int n = n0 + i; if (n >= Nn) n = Nn - 1;
                v[u] = homo4[((size_t)m * Nn + n) * 64 + d4];
            }
            #pragma unroll
            for (int u = 0; u < 4; u++) {
                int idx = (kk + u) * NTH + tid;
                int row = idx >> 6, d4 = idx & 63;
                uint2 p;
                p.x = packh2(v[u].x, v[u].y);
                p.y = packh2(v[u].z, v[u].w);
                sts64u(base + SM_A + swA(row * 512 + d4 * 8), p);
            }
        }
    }
    asm volatile("cp.async.wait_group 0;" ::: "memory");
    __syncthreads();

    // ---- GEMM: warp tile = 32 rows x 16 cols. wid -> (rb2 = wid&1, hc = wid>>1)
    const int rb2 = wid & 1;         // 32-row block
    const int hc  = wid >> 1;        // 16-col chunk of H (0..7)
    const int gr  = lane >> 2;       // fragment group row 0..7
    const int qk  = (lane & 3) * 2;  // fragment col pair within 8

    float acc[16];                   // [rowtile 2][ntile 2][4]
    #pragma unroll
    for (int i = 0; i < 16; i++) acc[i] = 0.0f;

    // A ldmatrix lane addressing (per rowtile)
    const int arow0 = rb2 * 32 + ((lane >> 3) & 1) * 8 + (lane & 7);
    const uint32_t aBase0 = base + SM_A + arow0 * 512;
    const uint32_t aBase1 = aBase0 + 16 * 512;
    const uint32_t aXor  = (uint32_t)((arow0 & 7) << 4);   // same row&7 for both tiles
    const uint32_t aK16  = (uint32_t)(((lane >> 4) & 1) * 16);
    // B ldmatrix lane addressing (transposed); XOR term invariant in ks
    const int lrow  = (lane & 7) + ((lane >> 3) & 1) * 8;
    const int bcol8 = ((lane >> 4) & 1) * 8;
    const uint32_t wBase = base + SM_W1 +
        (uint32_t)swW(lrow * 256 + (hc * 16 + bcol8) * 2);

    #pragma unroll
    for (int ks = 0; ks < 16; ks++) {
        uint32_t ka = ((uint32_t)(ks * 32) + aK16) ^ aXor;  // ks*32 doesn't touch XOR bits? (bit5+) overlap handled by unroll consts
        uint4 a0 = ldmx4(aBase0 + ((((uint32_t)ks * 32) + aK16) ^ aXor));
        uint4 a1 = ldmx4(aBase1 + ((((uint32_t)ks * 32) + aK16) ^ aXor));
        uint4 bb = ldmx4t(wBase + (uint32_t)ks * 4096);
        (void)ka;
        mma16816(acc + 0,  a0.x, a0.y, a0.z, a0.w, bb.x, bb.y);
        mma16816(acc + 4,  a0.x, a0.y, a0.z, a0.w, bb.z, bb.w);
        mma16816(acc + 8,  a1.x, a1.y, a1.z, a1.w, bb.x, bb.y);
        mma16816(acc + 12, a1.x, a1.y, a1.z, a1.w, bb.z, bb.w);
    }

    // ---------------- logits: tanh + dot(w2), quad reduce -------------------
    {
        float b1a[2], b1b[2], w2a[2], w2b[2];
        #pragma unroll
        for (int t = 0; t < 2; t++) {
            int col = hc * 16 + t * 8 + qk;
            b1a[t] = lds32(base + SM_B1 + col * 4);
            b1b[t] = lds32(base + SM_B1 + col * 4 + 4);
            w2a[t] = lds32(base + SM_W2 + col * 4);
            w2b[t] = lds32(base + SM_W2 + col * 4 + 4);
        }
        #pragma unroll
        for (int rt = 0; rt < 2; rt++) {
            float s0 = 0.0f, s1 = 0.0f;
            #pragma unroll
            for (int t = 0; t < 2; t++) {
                const float* a = acc + rt * 8 + t * 4;
                s0 += fast_tanh(a[0] + b1a[t]) * w2a[t]
                    + fast_tanh(a[1] + b1b[t]) * w2b[t];
                s1 += fast_tanh(a[2] + b1a[t]) * w2a[t]
                    + fast_tanh(a[3] + b1b[t]) * w2b[t];
            }
            s0 += __shfl_xor_sync(0xffffffffu, s0, 1);
            s0 += __shfl_xor_sync(0xffffffffu, s0, 2);
            s1 += __shfl_xor_sync(0xffffffffu, s1, 1);
            s1 += __shfl_xor_sync(0xffffffffu, s1, 2);
            if ((lane & 3) == 0) {
                int r = rb2 * 32 + rt * 16 + gr;
                sts32(base + SM_PART + (r * 8 + hc) * 4, s0);
                sts32(base + SM_PART + ((r + 8) * 8 + hc) * 4, s1);
            }
        }
    }
    __syncthreads();

    // ---------------- softmax over m (8 threads, one per node) --------------
    if (tid < TN) {
        float lg[8]; float mx = -1e30f;
        #pragma unroll
        for (int m = 0; m < 8; m++) {
            int r = m * 8 + tid;
            float4 pa = lds128(base + SM_PART + r * 32);
            float4 pb = lds128(base + SM_PART + r * 32 + 16);
            float s = (pa.x + pa.y + pa.z + pa.w) + (pb.x + pb.y + pb.z + pb.w);
            lg[m] = s; mx = fmaxf(mx, s);
        }
        float ss = 0.0f;
        #pragma unroll
        for (int m = 0; m < 8; m++) { lg[m] = __expf(lg[m] - mx); ss += lg[m]; }
        float inv = __fdividef(1.0f, ss);
        #pragma unroll
        for (int m = 0; m < 8; m++) sts32(base + SM_ATT + (m * 8 + tid) * 4, lg[m] * inv);
    }
    __syncthreads();

    // ------- weighted sum from fp16 A tile (2 warps per node, uint2/lane) ---
    {
        int node = wid >> 1;
        int c2 = (wid & 1) * 32 + lane;     // 8-byte chunk 0..63 -> one float4 out
        int n = n0 + node;
        if (n < Nn) {
            float a[8];
            #pragma unroll
            for (int m = 0; m < 8; m++) a[m] = lds32(base + SM_ATT + (m * 8 + node) * 4);
            float4 o = make_float4(0.f, 0.f, 0.f, 0.f);
            #pragma unroll
            for (int m = 0; m < 8; m++) {
                int row = m * 8 + node;
                uint2 rawv = lds64u(base + SM_A + swA(row * 512 + c2 * 8));
                float2 f0 = __half22float2(*reinterpret_cast<__half2*>(&rawv.x));
                float2 f1 = __half22float2(*reinterpret_cast<__half2*>(&rawv.y));
                o.x += a[m] * f0.x; o.y += a[m] * f0.y;
                o.z += a[m] * f1.x; o.w += a[m] * f1.y;
            }
            ((float4*)out)[(size_t)n * 64 + c2] = o;
        }
    }
}

extern "C" void kernel_launch(void* const* d_in, const int* in_sizes, int n_in,
                              void* d_out, int out_size) {
    const float* homo = (const float*)d_in[1];
    const float* W1   = (const float*)d_in[2];
    const float* b1   = (const float*)d_in[3];
    const float* W2   = (const float*)d_in[4];
    // b2 is a scalar added to every logit -> cancels in softmax over m; ignored.
    int Nn = in_sizes[0];

    cudaFuncSetAttribute(hete_kernel, cudaFuncAttributeMaxDynamicSharedMemorySize, SM_BYTES);
    prep_w1_kernel<<<(256 * 128 + 255) / 256, 256>>>(W1);
    int grid = (Nn + TN - 1) / TN;
    hete_kernel<<<grid, NTH, SM_BYTES>>>(homo, b1, W2, (float*)d_out, Nn);
}

// round 8
// speedup vs baseline: 1.5280x; 1.1951x over previous
#include <cuda_runtime.h>
#include <cuda_fp16.h>
#include <cstdint>

// out[n,d] = sum_m softmax_m( w2 . tanh(x[m,n,:] @ W1 + b1) ) * x[m,n,d]
// M=8, N=100000, D=256, H=128.
// Per CTA: 8 nodes x 8 metapaths = 64 GEMM rows, A tile fp16 in smem (MMA
// operand via ldmatrix AND weighted-sum source). Warp tile = 32 rows x 16 cols.
// B (W1) is pre-baked as an ldmatrix-fragment image in GLOBAL memory by a prep
// kernel; the GEMM fetches it with one coalesced LDG.128 per warp per k-step
// (L1-resident after the first tile). smem = 36 KB/CTA.

constexpr int TN  = 8;
constexpr int NTH = 512;

// smem offsets from 1024B-aligned base
constexpr int SM_A    = 0;        // 32768 B : A tile fp16 [64 rows][256 k], swizzled
constexpr int SM_PART = 32768;    //  2048 B : logit partials [64][8]
constexpr int SM_ATT  = 34816;    //   256 B
constexpr int SM_B1   = 35072;    //   512 B
constexpr int SM_W2   = 35584;    //   512 B
constexpr int SM_BYTES = 36096 + 1024;

// A swizzle: 512B rows; XOR byte bits[4:6] with row&7  (row = b>>9)
__host__ __device__ __forceinline__ int swA(int b) { return b ^ (((b >> 9) & 7) << 4); }
// W1 staging swizzle (prep kernel only): 256B rows; XOR bits[4:6] with (b>>8)&7
__host__ __device__ __forceinline__ int swW(int b) { return b ^ (((b >> 8) & 7) << 4); }

// ---------------- smem asm helpers (u32 shared addresses) ------------------
__device__ __forceinline__ float lds32(uint32_t a) {
    float v; asm volatile("ld.shared.f32 %0, [%1];" : "=f"(v) : "r"(a)); return v;
}
__device__ __forceinline__ void sts32(uint32_t a, float v) {
    asm volatile("st.shared.f32 [%0], %1;" :: "r"(a), "f"(v) : "memory");
}
__device__ __forceinline__ float4 lds128(uint32_t a) {
    float4 v;
    asm volatile("ld.shared.v4.f32 {%0,%1,%2,%3}, [%4];"
                 : "=f"(v.x), "=f"(v.y), "=f"(v.z), "=f"(v.w) : "r"(a));
    return v;
}
__device__ __forceinline__ void sts64u(uint32_t a, uint2 v) {
    asm volatile("st.shared.v2.b32 [%0], {%1,%2};" :: "r"(a), "r"(v.x), "r"(v.y) : "memory");
}
__device__ __forceinline__ uint2 lds64u(uint32_t a) {
    uint2 v;
    asm volatile("ld.shared.v2.b32 {%0,%1}, [%2];" : "=r"(v.x), "=r"(v.y) : "r"(a));
    return v;
}
__device__ __forceinline__ void sts16h(uint32_t a, __half v) {
    asm volatile("st.shared.b16 [%0], %1;" :: "r"(a), "h"(*(unsigned short*)&v) : "memory");
}
__device__ __forceinline__ uint4 ldmx4(uint32_t a) {           // non-transposed
    uint4 r;
    asm volatile("ldmatrix.sync.aligned.m8n8.x4.shared.b16 {%0,%1,%2,%3}, [%4];"
                 : "=r"(r.x), "=r"(r.y), "=r"(r.z), "=r"(r.w) : "r"(a));
    return r;
}
__device__ __forceinline__ uint4 ldmx4t(uint32_t a) {          // transposed
    uint4 r;
    asm volatile("ldmatrix.sync.aligned.m8n8.x4.trans.shared.b16 {%0,%1,%2,%3}, [%4];"
                 : "=r"(r.x), "=r"(r.y), "=r"(r.z), "=r"(r.w) : "r"(a));
    return r;
}
__device__ __forceinline__ void mma16816(float* c, uint32_t a0, uint32_t a1,
                                         uint32_t a2, uint32_t a3,
                                         uint32_t b0, uint32_t b1) {
    asm volatile("mma.sync.aligned.m16n8k16.row.col.f32.f16.f16.f32 "
                 "{%0,%1,%2,%3}, {%4,%5,%6,%7}, {%8,%9}, {%0,%1,%2,%3};"
                 : "+f"(c[0]), "+f"(c[1]), "+f"(c[2]), "+f"(c[3])
                 : "r"(a0), "r"(a1), "r"(a2), "r"(a3), "r"(b0), "r"(b1));
}
__device__ __forceinline__ uint32_t packh2(float lo, float hi) {
    __half2 h = __floats2half2_rn(lo, hi);
    return *reinterpret_cast<uint32_t*>(&h);
}
__device__ __forceinline__ float fast_tanh(float x) {
    float e = __expf(2.0f * x);
    return 1.0f - __fdividef(2.0f, e + 1.0f);
}

// ---- B fragment image: [set = ks*8+hc][lane 0..31] -> uint4 (64 KB) --------
__device__ __align__(16) uint4 g_w1frag[128 * 32];

// Prep: stage W1 fp16 swizzled in smem, then perform the exact ldmatrix the
// GEMM used to do, and store each lane's 4 fragment regs to global.
__global__ void prep_w1frag_kernel(const float* __restrict__ W1) {
    extern __shared__ char smraw[];
    uint32_t raw;
    asm("{ .reg .u64 t; cvta.to.shared.u64 t, %1; cvt.u32.u64 %0, t; }"
        : "=r"(raw) : "l"(smraw));
    const uint32_t base = (raw + 1023u) & ~1023u;

    const int tid = threadIdx.x, wid = tid >> 5, lane = tid & 31;

    // stage: W1 [D=256][H=128] row-major fp32 -> smem fp16 [k=256 rows][j=128], swW
    for (int idx = tid; idx < 256 * 128; idx += NTH) {
        int d = idx >> 7, j = idx & 127;
        __half h = __float2half_rn(W1[idx]);
        sts16h(base + (uint32_t)swW(d * 256 + j * 2), h);
    }
    __syncthreads();

    const int lrow  = (lane & 7) + ((lane >> 3) & 1) * 8;
    const int bcol8 = ((lane >> 4) & 1) * 8;
    #pragma unroll
    for (int u = 0; u < 8; u++) {
        int s  = wid * 8 + u;        // set id 0..127
        int ks = s >> 3, hc = s & 7;
        uint32_t wAddr = base +
            (uint32_t)swW((ks * 16 + lrow) * 256 + (hc * 16 + bcol8) * 2);
        uint4 bb = ldmx4t(wAddr);
        g_w1frag[s * 32 + lane] = bb;
    }
}

// --------------------------------- main -----------------------------------
__global__ __launch_bounds__(NTH, 2)
void hete_kernel(const float* __restrict__ homo, const float* __restrict__ b1g,
                 const float* __restrict__ w2g, float* __restrict__ out, int Nn) {
    extern __shared__ char smraw[];
    uint32_t raw;
    asm("{ .reg .u64 t; cvta.to.shared.u64 t, %1; cvt.u32.u64 %0, t; }"
        : "=r"(raw) : "l"(smraw));
    const uint32_t base = (raw + 1023u) & ~1023u;

    const int tid = threadIdx.x, wid = tid >> 5, lane = tid & 31;
    const int n0 = blockIdx.x * TN;

    if (tid < 128) {
        sts32(base + SM_B1 + tid * 4, b1g[tid]);
        sts32(base + SM_W2 + tid * 4, w2g[tid]);
    }

    // A tile fp16: 64 rows x 512B, swA swizzle. 4096 float4 / 512 thr = 8 each.
    {
        const float4* homo4 = (const float4*)homo;
        #pragma unroll 1
        for (int kk = 0; kk < 8; kk += 4) {
            float4 v[4];
            #pragma unroll
            for (int u = 0; u < 4; u++) {
                int idx = (kk + u) * NTH + tid;
                int row = idx >> 6, d4 = idx & 63;
                int m = row >> 3, i = row & 7;
                int n = n0 + i; if (n >= Nn) n = Nn - 1;
                v[u] = homo4[((size_t)m * Nn + n) * 64 + d4];
            }
            #pragma unroll
            for (int u = 0; u < 4; u++) {
                int idx = (kk + u) * NTH + tid;
                int row = idx >> 6, d4 = idx & 63;
                uint2 p;
                p.x = packh2(v[u].x, v[u].y);
                p.y = packh2(v[u].z, v[u].w);
                sts64u(base + SM_A + swA(row * 512 + d4 * 8), p);
            }
        }
    }
    __syncthreads();

    // ---- GEMM: warp tile = 32 rows x 16 cols. wid -> (rb2 = wid&1, hc = wid>>1)
    const int rb2 = wid & 1;         // 32-row block
    const int hc  = wid >> 1;        // 16-col chunk of H (0..7)
    const int gr  = lane >> 2;       // fragment group row 0..7
    const int qk  = (lane & 3) * 2;  // fragment col pair within 8

    float acc[16];                   // [rowtile 2][ntile 2][4]
    #pragma unroll
    for (int i = 0; i < 16; i++) acc[i] = 0.0f;

    // A ldmatrix lane addressing (per rowtile)
    const int arow0 = rb2 * 32 + ((lane >> 3) & 1) * 8 + (lane & 7);
    const uint32_t aBase0 = base + SM_A + arow0 * 512;
    const uint32_t aBase1 = aBase0 + 16 * 512;
    const uint32_t aXor  = (uint32_t)((arow0 & 7) << 4);
    const uint32_t aK16  = (uint32_t)(((lane >> 4) & 1) * 16);
    // B fragments from global image (L1-resident): per warp, per ks one LDG.128
    const uint4* __restrict__ gB = g_w1frag + hc * 32 + lane;   // stride 256/ks

    #pragma unroll
    for (int ks = 0; ks < 16; ks++) {
        uint4 bb = __ldg(gB + ks * 256);
        uint4 a0 = ldmx4(aBase0 + ((((uint32_t)ks * 32) + aK16) ^ aXor));
        uint4 a1 = ldmx4(aBase1 + ((((uint32_t)ks * 32) + aK16) ^ aXor));
        mma16816(acc + 0,  a0.x, a0.y, a0.z, a0.w, bb.x, bb.y);
        mma16816(acc + 4,  a0.x, a0.y, a0.z, a0.w, bb.z, bb.w);
        mma16816(acc + 8,  a1.x, a1.y, a1.z, a1.w, bb.x, bb.y);
        mma16816(acc + 12, a1.x, a1.y, a1.z, a1.w, bb.z, bb.w);
    }

    // ---------------- logits: tanh + dot(w2), quad reduce -------------------
    {
        float b1a[2], b1b[2], w2a[2], w2b[2];
        #pragma unroll
        for (int t = 0; t < 2; t++) {
            int col = hc * 16 + t * 8 + qk;
            b1a[t] = lds32(base + SM_B1 + col * 4);
            b1b[t] = lds32(base + SM_B1 + col * 4 + 4);
            w2a[t] = lds32(base + SM_W2 + col * 4);
            w2b[t] = lds32(base + SM_W2 + col * 4 + 4);
        }
        #pragma unroll
        for (int rt = 0; rt < 2; rt++) {
            float s0 = 0.0f, s1 = 0.0f;
            #pragma unroll
            for (int t = 0; t < 2; t++) {
                const float* a = acc + rt * 8 + t * 4;
                s0 += fast_tanh(a[0] + b1a[t]) * w2a[t]
                    + fast_tanh(a[1] + b1b[t]) * w2b[t];
                s1 += fast_tanh(a[2] + b1a[t]) * w2a[t]
                    + fast_tanh(a[3] + b1b[t]) * w2b[t];
            }
            s0 += __shfl_xor_sync(0xffffffffu, s0, 1);
            s0 += __shfl_xor_sync(0xffffffffu, s0, 2);
            s1 += __shfl_xor_sync(0xffffffffu, s1, 1);
            s1 += __shfl_xor_sync(0xffffffffu, s1, 2);
            if ((lane & 3) == 0) {
                int r = rb2 * 32 + rt * 16 + gr;
                sts32(base + SM_PART + (r * 8 + hc) * 4, s0);
                sts32(base + SM_PART + ((r + 8) * 8 + hc) * 4, s1);
            }
        }
    }
    __syncthreads();

    // ---------------- softmax over m (8 threads, one per node) --------------
    if (tid < TN) {
        float lg[8]; float mx = -1e30f;
        #pragma unroll
        for (int m = 0; m < 8; m++) {
            int r = m * 8 + tid;
            float4 pa = lds128(base + SM_PART + r * 32);
            float4 pb = lds128(base + SM_PART + r * 32 + 16);
            float s = (pa.x + pa.y + pa.z + pa.w) + (pb.x + pb.y + pb.z + pb.w);
            lg[m] = s; mx = fmaxf(mx, s);
        }
        float ss = 0.0f;
        #pragma unroll
        for (int m = 0; m < 8; m++) { lg[m] = __expf(lg[m] - mx); ss += lg[m]; }
        float inv = __fdividef(1.0f, ss);
        #pragma unroll
        for (int m = 0; m < 8; m++) sts32(base + SM_ATT + (m * 8 + tid) * 4, lg[m] * inv);
    }
    __syncthreads();

    // ------- weighted sum from fp16 A tile (2 warps per node, uint2/lane) ---
    {
        int node = wid >> 1;
        int c2 = (wid & 1) * 32 + lane;     // 8-byte chunk 0..63 -> one float4 out
        int n = n0 + node;
        if (n < Nn) {
            float a[8];
            #pragma unroll
            for (int m = 0; m < 8; m++) a[m] = lds32(base + SM_ATT + (m * 8 + node) * 4);
            float4 o = make_float4(0.f, 0.f, 0.f, 0.f);
            #pragma unroll
            for (int m = 0; m < 8; m++) {
                int row = m * 8 + node;
                uint2 rawv = lds64u(base + SM_A + swA(row * 512 + c2 * 8));
                float2 f0 = __half22float2(*reinterpret_cast<__half2*>(&rawv.x));
                float2 f1 = __half22float2(*reinterpret_cast<__half2*>(&rawv.y));
                o.x += a[m] * f0.x; o.y += a[m] * f0.y;
                o.z += a[m] * f1.x; o.w += a[m] * f1.y;
            }
            ((float4*)out)[(size_t)n * 64 + c2] = o;
        }
    }
}

extern "C" void kernel_launch(void* const* d_in, const int* in_sizes, int n_in,
                              void* d_out, int out_size) {
    const float* homo = (const float*)d_in[1];
    const float* W1   = (const float*)d_in[2];
    const float* b1   = (const float*)d_in[3];
    const float* W2   = (const float*)d_in[4];
    // b2 is a scalar added to every logit -> cancels in softmax over m; ignored.
    int Nn = in_sizes[0];

    const int prepSmem = 66560;  // 64KB stage + align slack
    cudaFuncSetAttribute(prep_w1frag_kernel,
                         cudaFuncAttributeMaxDynamicSharedMemorySize, prepSmem);
    cudaFuncSetAttribute(hete_kernel, cudaFuncAttributeMaxDynamicSharedMemorySize, SM_BYTES);
    prep_w1frag_kernel<<<1, NTH, prepSmem>>>(W1);
    int grid = (Nn + TN - 1) / TN;
    hete_kernel<<<grid, NTH, SM_BYTES>>>(homo, b1, W2, (float*)d_out, Nn);
}

// round 9
// speedup vs baseline: 1.8741x; 1.2265x over previous
#include <cuda_runtime.h>
#include <cuda_fp16.h>
#include <cstdint>

// out[n,d] = sum_m softmax_m( w2 . tanh(x[m,n,:] @ W1 + b1) ) * x[m,n,d]
// M=8, N=100000, D=256, H=128.
// Per CTA: 8 nodes x 8 metapaths = 64 GEMM rows, 256 threads (8 warps),
// warp tile 32 rows x 32 cols (acc[32]) -> A ldmatrix redundancy 4x not 8x.
// A tile fp16 in smem (MMA operand AND weighted-sum source). B (W1) pre-baked
// as ldmatrix-fragment image in GLOBAL memory (L1-resident). 4 CTAs/SM.

constexpr int TN  = 8;
constexpr int NTH = 256;

// smem offsets from 1024B-aligned base
constexpr int SM_A    = 0;        // 32768 B : A tile fp16 [64 rows][256 k], swizzled
constexpr int SM_PART = 32768;    //  1024 B : logit partials [64][4]
constexpr int SM_ATT  = 33792;    //   256 B
constexpr int SM_B1   = 34048;    //   512 B
constexpr int SM_W2   = 34560;    //   512 B
constexpr int SM_BYTES = 35072 + 1024;

// A swizzle: 512B rows; XOR byte bits[4:6] with row&7  (row = b>>9)
__host__ __device__ __forceinline__ int swA(int b) { return b ^ (((b >> 9) & 7) << 4); }
// W1 staging swizzle (prep kernel only): 256B rows; XOR bits[4:6] with (b>>8)&7
__host__ __device__ __forceinline__ int swW(int b) { return b ^ (((b >> 8) & 7) << 4); }

// ---------------- smem asm helpers (u32 shared addresses) ------------------
__device__ __forceinline__ float lds32(uint32_t a) {
    float v; asm volatile("ld.shared.f32 %0, [%1];" : "=f"(v) : "r"(a)); return v;
}
__device__ __forceinline__ void sts32(uint32_t a, float v) {
    asm volatile("st.shared.f32 [%0], %1;" :: "r"(a), "f"(v) : "memory");
}
__device__ __forceinline__ float4 lds128(uint32_t a) {
    float4 v;
    asm volatile("ld.shared.v4.f32 {%0,%1,%2,%3}, [%4];"
                 : "=f"(v.x), "=f"(v.y), "=f"(v.z), "=f"(v.w) : "r"(a));
    return v;
}
__device__ __forceinline__ void sts64u(uint32_t a, uint2 v) {
    asm volatile("st.shared.v2.b32 [%0], {%1,%2};" :: "r"(a), "r"(v.x), "r"(v.y) : "memory");
}
__device__ __forceinline__ uint2 lds64u(uint32_t a) {
    uint2 v;
    asm volatile("ld.shared.v2.b32 {%0,%1}, [%2];" : "=r"(v.x), "=r"(v.y) : "r"(a));
    return v;
}
__device__ __forceinline__ void sts16h(uint32_t a, __half v) {
    asm volatile("st.shared.b16 [%0], %1;" :: "r"(a), "h"(*(unsigned short*)&v) : "memory");
}
__device__ __forceinline__ uint4 ldmx4(uint32_t a) {           // non-transposed
    uint4 r;
    asm volatile("ldmatrix.sync.aligned.m8n8.x4.shared.b16 {%0,%1,%2,%3}, [%4];"
                 : "=r"(r.x), "=r"(r.y), "=r"(r.z), "=r"(r.w) : "r"(a));
    return r;
}
__device__ __forceinline__ uint4 ldmx4t(uint32_t a) {          // transposed
    uint4 r;
    asm volatile("ldmatrix.sync.aligned.m8n8.x4.trans.shared.b16 {%0,%1,%2,%3}, [%4];"
                 : "=r"(r.x), "=r"(r.y), "=r"(r.z), "=r"(r.w) : "r"(a));
    return r;
}
__device__ __forceinline__ void mma16816(float* c, uint32_t a0, uint32_t a1,
                                         uint32_t a2, uint32_t a3,
                                         uint32_t b0, uint32_t b1) {
    asm volatile("mma.sync.aligned.m16n8k16.row.col.f32.f16.f16.f32 "
                 "{%0,%1,%2,%3}, {%4,%5,%6,%7}, {%8,%9}, {%0,%1,%2,%3};"
                 : "+f"(c[0]), "+f"(c[1]), "+f"(c[2]), "+f"(c[3])
                 : "r"(a0), "r"(a1), "r"(a2), "r"(a3), "r"(b0), "r"(b1));
}
__device__ __forceinline__ uint32_t packh2(float lo, float hi) {
    __half2 h = __floats2half2_rn(lo, hi);
    return *reinterpret_cast<uint32_t*>(&h);
}
__device__ __forceinline__ float fast_tanh(float x) {
    float e = __expf(2.0f * x);
    return 1.0f - __fdividef(2.0f, e + 1.0f);
}

// ---- B fragment image: [set = ks*8+hc][lane 0..31] -> uint4 (64 KB) --------
__device__ __align__(16) uint4 g_w1frag[128 * 32];

// Prep: stage W1 fp16 swizzled in smem, perform the exact GEMM ldmatrix, and
// store each lane's 4 fragment regs to global.
__global__ void prep_w1frag_kernel(const float* __restrict__ W1) {
    extern __shared__ char smraw[];
    uint32_t raw;
    asm("{ .reg .u64 t; cvta.to.shared.u64 t, %1; cvt.u32.u64 %0, t; }"
        : "=r"(raw) : "l"(smraw));
    const uint32_t base = (raw + 1023u) & ~1023u;

    const int tid = threadIdx.x, wid = tid >> 5, lane = tid & 31;

    for (int idx = tid; idx < 256 * 128; idx += 512) {
        int d = idx >> 7, j = idx & 127;
        __half h = __float2half_rn(W1[idx]);
        sts16h(base + (uint32_t)swW(d * 256 + j * 2), h);
    }
    __syncthreads();

    const int lrow  = (lane & 7) + ((lane >> 3) & 1) * 8;
    const int bcol8 = ((lane >> 4) & 1) * 8;
    #pragma unroll
    for (int u = 0; u < 8; u++) {
        int s  = wid * 8 + u;        // set id 0..127
        int ks = s >> 3, hc = s & 7;
        uint32_t wAddr = base +
            (uint32_t)swW((ks * 16 + lrow) * 256 + (hc * 16 + bcol8) * 2);
        uint4 bb = ldmx4t(wAddr);
        g_w1frag[s * 32 + lane] = bb;
    }
}

// --------------------------------- main -----------------------------------
__global__ __launch_bounds__(NTH, 4)
void hete_kernel(const float* __restrict__ homo, const float* __restrict__ b1g,
                 const float* __restrict__ w2g, float* __restrict__ out, int Nn) {
    extern __shared__ char smraw[];
    uint32_t raw;
    asm("{ .reg .u64 t; cvta.to.shared.u64 t, %1; cvt.u32.u64 %0, t; }"
        : "=r"(raw) : "l"(smraw));
    const uint32_t base = (raw + 1023u) & ~1023u;

    const int tid = threadIdx.x, wid = tid >> 5, lane = tid & 31;
    const int n0 = blockIdx.x * TN;

    if (tid < 128) {
        sts32(base + SM_B1 + tid * 4, b1g[tid]);
        sts32(base + SM_W2 + tid * 4, w2g[tid]);
    }

    // A tile fp16: 64 rows x 512B, swA swizzle. 4096 float4 / 256 thr = 16 each.
    {
        const float4* homo4 = (const float4*)homo;
        #pragma unroll 1
        for (int kk = 0; kk < 16; kk += 4) {
            float4 v[4];
            #pragma unroll
            for (int u = 0; u < 4; u++) {
                int idx = (kk + u) * NTH + tid;
                int row = idx >> 6, d4 = idx & 63;
                int m = row >> 3, i = row & 7;
                int n = n0 + i; if (n >= Nn) n = Nn - 1;
                v[u] = homo4[((size_t)m * Nn + n) * 64 + d4];
            }
            #pragma unroll
            for (int u = 0; u < 4; u++) {
                int idx = (kk + u) * NTH + tid;
                int row = idx >> 6, d4 = idx & 63;
                uint2 p;
                p.x = packh2(v[u].x, v[u].y);
                p.y = packh2(v[u].z, v[u].w);
                sts64u(base + SM_A + swA(row * 512 + d4 * 8), p);
            }
        }
    }
    __syncthreads();

    // ---- GEMM: warp tile = 32 rows x 32 cols. wid -> (rb2 = wid&1, hq = wid>>1)
    const int rb2 = wid & 1;         // 32-row block
    const int hq  = wid >> 1;        // 32-col quarter of H (0..3)
    const int gr  = lane >> 2;       // fragment group row 0..7
    const int qk  = (lane & 3) * 2;  // fragment col pair within 8

    float acc[32];                   // [rowtile 2][ntile 4][4]
    #pragma unroll
    for (int i = 0; i < 32; i++) acc[i] = 0.0f;

    // A ldmatrix lane addressing (per rowtile)
    const int arow0 = rb2 * 32 + ((lane >> 3) & 1) * 8 + (lane & 7);
    const uint32_t aBase0 = base + SM_A + arow0 * 512;
    const uint32_t aBase1 = aBase0 + 16 * 512;
    const uint32_t aXor  = (uint32_t)((arow0 & 7) << 4);
    const uint32_t aK16  = (uint32_t)(((lane >> 4) & 1) * 16);
    // B fragments from global image (L1-resident): two 16-col sets per warp
    const uint4* __restrict__ gB = g_w1frag + (hq * 2) * 32 + lane;  // +32 = next set

    #pragma unroll
    for (int ks = 0; ks < 16; ks++) {
        uint4 b0 = __ldg(gB + ks * 256);
        uint4 b1 = __ldg(gB + ks * 256 + 32);
        uint32_t ko = (((uint32_t)ks * 32) + aK16) ^ aXor;
        uint4 a0 = ldmx4(aBase0 + ko);
        uint4 a1 = ldmx4(aBase1 + ko);
        mma16816(acc + 0,  a0.x, a0.y, a0.z, a0.w, b0.x, b0.y);
        mma16816(acc + 4,  a0.x, a0.y, a0.z, a0.w, b0.z, b0.w);
        mma16816(acc + 8,  a0.x, a0.y, a0.z, a0.w, b1.x, b1.y);
        mma16816(acc + 12, a0.x, a0.y, a0.z, a0.w, b1.z, b1.w);
        mma16816(acc + 16, a1.x, a1.y, a1.z, a1.w, b0.x, b0.y);
        mma16816(acc + 20, a1.x, a1.y, a1.z, a1.w, b0.z, b0.w);
        mma16816(acc + 24, a1.x, a1.y, a1.z, a1.w, b1.x, b1.y);
        mma16816(acc + 28, a1.x, a1.y, a1.z, a1.w, b1.z, b1.w);
    }

    // ---------------- logits: tanh + dot(w2), quad reduce -------------------
    {
        float b1a[4], b1b[4], w2a[4], w2b[4];
        #pragma unroll
        for (int t = 0; t < 4; t++) {
            int col = hq * 32 + t * 8 + qk;
            b1a[t] = lds32(base + SM_B1 + col * 4);
            b1b[t] = lds32(base + SM_B1 + col * 4 + 4);
            w2a[t] = lds32(base + SM_W2 + col * 4);
            w2b[t] = lds32(base + SM_W2 + col * 4 + 4);
        }
        #pragma unroll
        for (int rt = 0; rt < 2; rt++) {
            float s0 = 0.0f, s1 = 0.0f;
            #pragma unroll
            for (int t = 0; t < 4; t++) {
                const float* a = acc + rt * 16 + t * 4;
                s0 += fast_tanh(a[0] + b1a[t]) * w2a[t]
                    + fast_tanh(a[1] + b1b[t]) * w2b[t];
                s1 += fast_tanh(a[2] + b1a[t]) * w2a[t]
                    + fast_tanh(a[3] + b1b[t]) * w2b[t];
            }
            s0 += __shfl_xor_sync(0xffffffffu, s0, 1);
            s0 += __shfl_xor_sync(0xffffffffu, s0, 2);
            s1 += __shfl_xor_sync(0xffffffffu, s1, 1);
            s1 += __shfl_xor_sync(0xffffffffu, s1, 2);
            if ((lane & 3) == 0) {
                int r = rb2 * 32 + rt * 16 + gr;
                sts32(base + SM_PART + (r * 4 + hq) * 4, s0);
                sts32(base + SM_PART + ((r + 8) * 4 + hq) * 4, s1);
            }
        }
    }
    __syncthreads();

    // ---------------- softmax over m (8 threads, one per node) --------------
    if (tid < TN) {
        float lg[8]; float mx = -1e30f;
        #pragma unroll
        for (int m = 0; m < 8; m++) {
            int r = m * 8 + tid;
            float4 pa = lds128(base + SM_PART + r * 16);
            float s = pa.x + pa.y + pa.z + pa.w;
            lg[m] = s; mx = fmaxf(mx, s);
        }
        float ss = 0.0f;
        #pragma unroll
        for (int m = 0; m < 8; m++) { lg[m] = __expf(lg[m] - mx); ss += lg[m]; }
        float inv = __fdividef(1.0f, ss);
        #pragma unroll
        for (int m = 0; m < 8; m++) sts32(base + SM_ATT + (m * 8 + tid) * 4, lg[m] * inv);
    }
    __syncthreads();

    // ------- weighted sum from fp16 A tile (1 warp per node, 2 halves) ------
    {
        int node = wid;                 // 0..7
        int n = n0 + node;
        if (n < Nn) {
            float a[8];
            #pragma unroll
            for (int m = 0; m < 8; m++) a[m] = lds32(base + SM_ATT + (m * 8 + node) * 4);
            #pragma unroll
            for (int half = 0; half < 2; half++) {
                int c2 = lane + 32 * half;      // 8-byte chunk 0..63
                float4 o = make_float4(0.f, 0.f, 0.f, 0.f);
                #pragma unroll
                for (int m = 0; m < 8; m++) {
                    int row = m * 8 + node;
                    uint2 rawv = lds64u(base + SM_A + swA(row * 512 + c2 * 8));
                    float2 f0 = __half22float2(*reinterpret_cast<__half2*>(&rawv.x));
                    float2 f1 = __half22float2(*reinterpret_cast<__half2*>(&rawv.y));
                    o.x += a[m] * f0.x; o.y += a[m] * f0.y;
                    o.z += a[m] * f1.x; o.w += a[m] * f1.y;
                }
                ((float4*)out)[(size_t)n * 64 + c2] = o;
            }
        }
    }
}

extern "C" void kernel_launch(void* const* d_in, const int* in_sizes, int n_in,
                              void* d_out, int out_size) {
    const float* homo = (const float*)d_in[1];
    const float* W1   = (const float*)d_in[2];
    const float* b1   = (const float*)d_in[3];
    const float* W2   = (const float*)d_in[4];
    // b2 is a scalar added to every logit -> cancels in softmax over m; ignored.
    int Nn = in_sizes[0];

    const int prepSmem = 66560;  // 64KB stage + align slack
    cudaFuncSetAttribute(prep_w1frag_kernel,
                         cudaFuncAttributeMaxDynamicSharedMemorySize, prepSmem);
    cudaFuncSetAttribute(hete_kernel, cudaFuncAttributeMaxDynamicSharedMemorySize, SM_BYTES);
    prep_w1frag_kernel<<<1, 512, prepSmem>>>(W1);
    int grid = (Nn + TN - 1) / TN;
    hete_kernel<<<grid, NTH, SM_BYTES>>>(homo, b1, W2, (float*)d_out, Nn);
}